// round 16
// baseline (speedup 1.0000x reference)
#include <cuda_runtime.h>
#include <cuda_bf16.h>
#include <cstdint>

#define BB 4
#define NN 1024
#define FF 256
#define HH 8
#define NF (NN*FF)

// ---------------- scratch (no allocations allowed) ----------------
__device__ float p0_buf [BB*NN*FF];
__device__ float p1_buf [BB*NN*FF];
__device__ float y_buf  [BB*NN*FF];
__device__ float ex_buf [4*BB*HH*NN];   // es, es2, ed, ed2  each [bh][n]
__device__ float den_buf[BB*HH*NN];
__device__ unsigned adjb_buf [NN*32];   // row bits:  adjb[i][jw]
__device__ unsigned adjbT_buf[NN*32];   // col bits:  adjbT[j][iw]
__device__ __nv_bfloat16 gthi_buf[BB*HH*32*NN];   // G^T hi  [bh][d][j]
__device__ __nv_bfloat16 gtlo_buf[BB*HH*32*NN];   // G^T lo

// ---------------- f32x2 helpers ----------------
__device__ __forceinline__ unsigned long long pack2(float a, float b) {
    unsigned long long r;
    asm("mov.b64 %0, {%1, %2};" : "=l"(r) : "f"(a), "f"(b));
    return r;
}
__device__ __forceinline__ void ffma2(unsigned long long& acc,
                                      unsigned long long a, unsigned long long b) {
    asm("fma.rn.f32x2 %0, %1, %2, %0;" : "+l"(acc) : "l"(a), "l"(b));
}
union F4U2 { float4 f; ulonglong2 u; };

// ---------------- mma helpers ----------------
__device__ __forceinline__ uint32_t smem_u32(const void* p) {
    uint32_t a;
    asm("{ .reg .u64 t; cvta.to.shared.u64 t, %1; cvt.u32.u64 %0, t; }" : "=r"(a) : "l"(p));
    return a;
}
__device__ __forceinline__ uint32_t cvt2(float hi, float lo) {
    uint32_t r;
    asm("cvt.rn.bf16x2.f32 %0, %1, %2;" : "=r"(r) : "f"(hi), "f"(lo));
    return r;
}
__device__ __forceinline__ void ldm_x4(uint32_t& r0, uint32_t& r1, uint32_t& r2,
                                       uint32_t& r3, uint32_t addr) {
    asm volatile("ldmatrix.sync.aligned.m8n8.x4.shared.b16 {%0,%1,%2,%3}, [%4];"
                 : "=r"(r0), "=r"(r1), "=r"(r2), "=r"(r3) : "r"(addr));
}
__device__ __forceinline__ void mma16816(float* c, uint32_t a0, uint32_t a1,
                                         uint32_t a2, uint32_t a3,
                                         uint32_t b0, uint32_t b1) {
    asm volatile(
        "mma.sync.aligned.m16n8k16.row.col.f32.bf16.bf16.f32 "
        "{%0,%1,%2,%3}, {%4,%5,%6,%7}, {%8,%9}, {%0,%1,%2,%3};"
        : "+f"(c[0]), "+f"(c[1]), "+f"(c[2]), "+f"(c[3])
        : "r"(a0), "r"(a1), "r"(a2), "r"(a3), "r"(b0), "r"(b1));
}

// ---------------- fused GEMM + gt-transpose + src/dst exp tables + den zero ----------------
// C tile [64 m x 32 o] = one head. grid (8, 64), 128 threads, 4x4 micro.
__global__ __launch_bounds__(128) void gemm_fused(const float* __restrict__ A,
                                                  const float* __restrict__ W,
                                                  const float* __restrict__ av,
                                                  float* __restrict__ es,
                                                  float* __restrict__ es2,
                                                  float* __restrict__ ed,
                                                  float* __restrict__ ed2,
                                                  __nv_bfloat16* __restrict__ gthi,
                                                  __nv_bfloat16* __restrict__ gtlo,
                                                  float* __restrict__ den) {
    __shared__ float As[16][68];
    __shared__ float Bs[16][36];
    __shared__ uint32_t T[32][65];   // [o_local][m_local] packed hi|lo bf16
    const int m0 = blockIdx.y * 64;
    const int o0 = blockIdx.x * 32;
    const int tid = threadIdx.x;
    const int tx = tid & 7;          // o micro col group (4 each)
    const int ty = tid >> 3;         // m micro row group (4 each), 0..15

    // zero den
    const int gtid = (blockIdx.y * 8 + blockIdx.x) * 128 + tid;
    if (gtid < BB * HH * NN) den[gtid] = 0.f;

    unsigned long long acc2[4][2];
    #pragma unroll
    for (int a = 0; a < 4; a++) { acc2[a][0] = 0ull; acc2[a][1] = 0ull; }
    for (int k0 = 0; k0 < 256; k0 += 16) {
        const int c = tid & 15;
        const int r = tid >> 4;      // 0..7
        #pragma unroll
        for (int rr = 0; rr < 64; rr += 8)
            As[c][r + rr] = A[(m0 + r + rr) * 256 + k0 + c];
        #pragma unroll
        for (int rr = 0; rr < 32; rr += 8)
            Bs[c][r + rr] = W[(o0 + r + rr) * 256 + k0 + c];
        __syncthreads();
        #pragma unroll
        for (int kk = 0; kk < 16; kk++) {
            F4U2 a4, b4;
            a4.f = *(const float4*)&As[kk][ty * 4];
            b4.f = *(const float4*)&Bs[kk][tx * 4];
            const unsigned long long ap0 = pack2(a4.f.x, a4.f.x);
            const unsigned long long ap1 = pack2(a4.f.y, a4.f.y);
            const unsigned long long ap2 = pack2(a4.f.z, a4.f.z);
            const unsigned long long ap3 = pack2(a4.f.w, a4.f.w);
            ffma2(acc2[0][0], ap0, b4.u.x); ffma2(acc2[0][1], ap0, b4.u.y);
            ffma2(acc2[1][0], ap1, b4.u.x); ffma2(acc2[1][1], ap1, b4.u.y);
            ffma2(acc2[2][0], ap2, b4.u.x); ffma2(acc2[2][1], ap2, b4.u.y);
            ffma2(acc2[3][0], ap3, b4.u.x); ffma2(acc2[3][1], ap3, b4.u.y);
        }
        __syncthreads();
    }

    const int b  = m0 >> 10;
    const int j0 = m0 & 1023;
    const int h0 = o0 >> 5;          // single head for this block

    float aws[4], awd[4];
    #pragma unroll
    for (int c = 0; c < 4; ++c) {
        const int d = tx * 4 + c;    // 0..31
        aws[c] = av[d];
        awd[c] = av[32 + d];
    }

    float vv[4][4];
    #pragma unroll
    for (int a = 0; a < 4; a++) {
        F4U2 o;
        o.u.x = acc2[a][0];
        o.u.y = acc2[a][1];
        vv[a][0] = o.f.x; vv[a][1] = o.f.y; vv[a][2] = o.f.z; vv[a][3] = o.f.w;
        #pragma unroll
        for (int c = 0; c < 4; ++c) {
            const __nv_bfloat16 hi = __float2bfloat16(vv[a][c]);
            const __nv_bfloat16 lo = __float2bfloat16(vv[a][c] - __bfloat162float(hi));
            T[tx * 4 + c][ty * 4 + a] = (uint32_t)__bfloat16_as_ushort(hi)
                                      | ((uint32_t)__bfloat16_as_ushort(lo) << 16);
        }
    }

    // src/dst head-sums: 8 tx-lanes hold the head's 32 d-values
    #pragma unroll
    for (int a = 0; a < 4; a++) {
        float s = vv[a][0] * aws[0] + vv[a][1] * aws[1]
                + vv[a][2] * aws[2] + vv[a][3] * aws[3];
        float d = vv[a][0] * awd[0] + vv[a][1] * awd[1]
                + vv[a][2] * awd[2] + vv[a][3] * awd[3];
        #pragma unroll
        for (int off = 4; off; off >>= 1) {
            s += __shfl_down_sync(0xFFFFFFFFu, s, off, 8);
            d += __shfl_down_sync(0xFFFFFFFFu, d, off, 8);
        }
        if (tx == 0) {
            const int n = j0 + ty * 4 + a;
            const int idx = (b * HH + h0) * NN + n;
            es [idx] = __expf(s);
            es2[idx] = __expf(0.2f * s);
            ed [idx] = __expf(d);
            ed2[idx] = __expf(0.2f * d);
        }
    }

    __syncthreads();
    {
        const int dl = tid >> 2;          // 0..31 (d within head)
        const int mq = (tid & 3) * 16;
        __align__(16) unsigned short his[16];
        __align__(16) unsigned short los[16];
        #pragma unroll
        for (int k = 0; k < 16; ++k) {
            const uint32_t v = T[dl][mq + k];
            his[k] = (unsigned short)(v & 0xFFFF);
            los[k] = (unsigned short)(v >> 16);
        }
        const size_t base = (size_t)((b * HH + h0) * 32 + dl) * NN + j0 + mq;
        *(uint4*)&gthi[base]     = ((uint4*)his)[0];
        *(uint4*)&gthi[base + 8] = ((uint4*)his)[1];
        *(uint4*)&gtlo[base]     = ((uint4*)los)[0];
        *(uint4*)&gtlo[base + 8] = ((uint4*)los)[1];
    }
}

// ---------------- adj -> row + column bitmasks (one kernel) ----------------
__global__ __launch_bounds__(1024) void adjprep_k(const int* __restrict__ adj,
                                                  unsigned* __restrict__ adjb,
                                                  unsigned* __restrict__ adjbT) {
    __shared__ unsigned tileW[32][33];
    const int lane = threadIdx.x;
    const int wy   = threadIdx.y;
    const int i    = blockIdx.x * 32 + wy;
    #pragma unroll 4
    for (int w = 0; w < 32; ++w) {
        const int v = adj[i * 1024 + w * 32 + lane];
        const unsigned m = __ballot_sync(0xFFFFFFFFu, v != 0);
        if (lane == 0) {
            adjb[i * 32 + w] = m;
            tileW[wy][w] = m;
        }
    }
    __syncthreads();
    const unsigned wrd = tileW[lane][wy];
    #pragma unroll 4
    for (int c = 0; c < 32; ++c) {
        const unsigned m2 = __ballot_sync(0xFFFFFFFFu, (wrd >> c) & 1u);
        if (lane == c) adjbT[(wy * 32 + c) * 32 + blockIdx.x] = m2;
    }
}

// ---------------- den[bh][j] += sum_{i chunk} adj * max(es*ed, es2*ed2) ----------------
__global__ __launch_bounds__(512) void denom_k(const unsigned* __restrict__ adjbT,
                                               const float* __restrict__ es,
                                               const float* __restrict__ es2,
                                               const float* __restrict__ ed,
                                               const float* __restrict__ ed2,
                                               float* __restrict__ den) {
    __shared__ float2 essv[64];
    const int b = blockIdx.z, h = blockIdx.y, bh = b * HH + h;
    const int ic = blockIdx.x * 64;
    const int tid = threadIdx.x;
    if (tid < 64) essv[tid] = make_float2(es[bh * NN + ic + tid],
                                          es2[bh * NN + ic + tid]);
    __syncthreads();
    const int j0 = tid, j1 = tid + 512;
    const float edj0 = ed[bh * NN + j0], ed2j0 = ed2[bh * NN + j0];
    const float edj1 = ed[bh * NN + j1], ed2j1 = ed2[bh * NN + j1];
    const int wbase = ic >> 5;
    float a0 = 0.f, a1 = 0.f;
    #pragma unroll
    for (int w = 0; w < 2; ++w) {
        const unsigned word0 = adjbT[(size_t)j0 * 32 + wbase + w];
        const unsigned word1 = adjbT[(size_t)j1 * 32 + wbase + w];
        #pragma unroll
        for (int k = 0; k < 32; ++k) {
            const float2 e = essv[w * 32 + k];
            const float v0 = fmaxf(e.x * edj0, e.y * ed2j0);
            const float v1 = fmaxf(e.x * edj1, e.y * ed2j1);
            if ((word0 >> k) & 1u) a0 += v0;
            if ((word1 >> k) & 1u) a1 += v1;
        }
    }
    atomicAdd(&den[bh * NN + j0], a0);
    atomicAdd(&den[bh * NN + j1], a1);
}

// ---------------- attention via mma.sync bf16 (trunc-hi/lo 3-term), j-split x2 ----------------
#define GROW 272

__device__ __forceinline__ float wv(float esr, float es2r, float2 e,
                                    unsigned bits, int c) {
    const float v = fmaxf(esr * e.x, es2r * e.y);
    return ((bits >> c) & 1u) ? v : 0.0f;
}

__global__ __launch_bounds__(256) void attn_k(const unsigned* __restrict__ adjb,
                                              const float* __restrict__ es,
                                              const float* __restrict__ es2,
                                              const float* __restrict__ ed,
                                              const float* __restrict__ ed2,
                                              const float* __restrict__ den,
                                              const __nv_bfloat16* __restrict__ gthi,
                                              const __nv_bfloat16* __restrict__ gtlo,
                                              float* __restrict__ part0,
                                              float* __restrict__ part1) {
    __shared__ __align__(16) char GsHi[32 * GROW];
    __shared__ __align__(16) char GsLo[32 * GROW];
    __shared__ float2 eds[NN / 2];
    __shared__ unsigned adjw[128][17];
    const int b = blockIdx.z;
    const int h = blockIdx.y & 7, jh = blockIdx.y >> 3;
    const int bh = b * HH + h;
    const int jbase = jh * (NN / 2);
    const int i0 = blockIdx.x * 128;
    const int tid = threadIdx.x, wid = tid >> 5, lane = tid & 31;
    const int g = lane >> 2, t = lane & 3;

    for (int j = tid; j < NN / 2; j += 256) {
        const float r = 1.0f / den[bh * NN + jbase + j];
        eds[j] = make_float2(ed[bh * NN + jbase + j] * r,
                             ed2[bh * NN + jbase + j] * r);
    }
    for (int k = tid; k < 128 * 16; k += 256)
        adjw[k >> 4][k & 15] = adjb[(size_t)(i0 + (k >> 4)) * 32 + jh * 16 + (k & 15)];

    const int r0 = i0 + wid * 16 + g;
    const float es_0  = es [bh * NN + r0];
    const float es_1  = es [bh * NN + r0 + 8];
    const float es2_0 = es2[bh * NN + r0];
    const float es2_1 = es2[bh * NN + r0 + 8];

    float acc[4][4] = {};
    const uint32_t gsHiA = smem_u32(GsHi), gsLoA = smem_u32(GsLo);
    const int d_l  = ((lane >> 4) & 1) * 8 + (lane & 7);
    const int jo_l = ((lane >> 3) & 1) * 8;
    const uint32_t lmoff = (uint32_t)(d_l * GROW + jo_l * 2);

    const __nv_bfloat16* ghb = gthi + (size_t)bh * 32 * NN + jbase;
    const __nv_bfloat16* glb = gtlo + (size_t)bh * 32 * NN + jbase;

    for (int ck = 0; ck < NN / 2; ck += 128) {
        __syncthreads();
        #pragma unroll
        for (int q = 0; q < 2; ++q) {
            const int idx = tid + q * 256;
            const int d = idx >> 4, c16 = idx & 15;
            const uint4 vh = *(const uint4*)(ghb + (size_t)d * NN + ck + c16 * 8);
            const uint4 vl = *(const uint4*)(glb + (size_t)d * NN + ck + c16 * 8);
            *(uint4*)(GsHi + d * GROW + c16 * 16) = vh;
            *(uint4*)(GsLo + d * GROW + c16 * 16) = vl;
        }
        __syncthreads();
        unsigned cw0[4], cw1[4];
        #pragma unroll
        for (int w = 0; w < 4; ++w) {
            cw0[w] = adjw[wid * 16 + g][(ck >> 5) + w];
            cw1[w] = adjw[wid * 16 + g + 8][(ck >> 5) + w];
        }
        #pragma unroll
        for (int kk = 0; kk < 128; kk += 16) {
            uint32_t bh01[4], bh23[4], bl01[4], bl23[4];
            ldm_x4(bh01[0], bh01[1], bh01[2], bh01[3], gsHiA + lmoff + kk * 2);
            ldm_x4(bh23[0], bh23[1], bh23[2], bh23[3], gsHiA + lmoff + kk * 2 + 16 * GROW);
            ldm_x4(bl01[0], bl01[1], bl01[2], bl01[3], gsLoA + lmoff + kk * 2);
            ldm_x4(bl23[0], bl23[1], bl23[2], bl23[3], gsLoA + lmoff + kk * 2 + 16 * GROW);
            const unsigned bits0 = cw0[kk >> 5] >> (kk & 31);
            const unsigned bits1 = cw1[kk >> 5] >> (kk & 31);
            const int jc = ck + kk;
            const float2 e0 = eds[jc + 2 * t];
            const float2 e1 = eds[jc + 2 * t + 1];
            const float2 e2 = eds[jc + 2 * t + 8];
            const float2 e3 = eds[jc + 2 * t + 9];
            const float w00 = wv(es_0, es2_0, e0, bits0, 2 * t);
            const float w01 = wv(es_0, es2_0, e1, bits0, 2 * t + 1);
            const float w02 = wv(es_0, es2_0, e2, bits0, 2 * t + 8);
            const float w03 = wv(es_0, es2_0, e3, bits0, 2 * t + 9);
            const float w10 = wv(es_1, es2_1, e0, bits1, 2 * t);
            const float w11 = wv(es_1, es2_1, e1, bits1, 2 * t + 1);
            const float w12 = wv(es_1, es2_1, e2, bits1, 2 * t + 8);
            const float w13 = wv(es_1, es2_1, e3, bits1, 2 * t + 9);
            // hi = truncated top-16 bits (W >= 0): single PRMT per pair, no cvt
            const uint32_t u00 = __float_as_uint(w00), u01 = __float_as_uint(w01);
            const uint32_t u02 = __float_as_uint(w02), u03 = __float_as_uint(w03);
            const uint32_t u10 = __float_as_uint(w10), u11 = __float_as_uint(w11);
            const uint32_t u12 = __float_as_uint(w12), u13 = __float_as_uint(w13);
            const uint32_t ahi0 = __byte_perm(u00, u01, 0x7632);
            const uint32_t ahi1 = __byte_perm(u10, u11, 0x7632);
            const uint32_t ahi2 = __byte_perm(u02, u03, 0x7632);
            const uint32_t ahi3 = __byte_perm(u12, u13, 0x7632);
            const uint32_t alo0 = cvt2(w01 - __uint_as_float(u01 & 0xFFFF0000u),
                                       w00 - __uint_as_float(u00 & 0xFFFF0000u));
            const uint32_t alo1 = cvt2(w11 - __uint_as_float(u11 & 0xFFFF0000u),
                                       w10 - __uint_as_float(u10 & 0xFFFF0000u));
            const uint32_t alo2 = cvt2(w03 - __uint_as_float(u03 & 0xFFFF0000u),
                                       w02 - __uint_as_float(u02 & 0xFFFF0000u));
            const uint32_t alo3 = cvt2(w13 - __uint_as_float(u13 & 0xFFFF0000u),
                                       w12 - __uint_as_float(u12 & 0xFFFF0000u));
            mma16816(acc[0], ahi0, ahi1, ahi2, ahi3, bh01[0], bh01[1]);
            mma16816(acc[1], ahi0, ahi1, ahi2, ahi3, bh01[2], bh01[3]);
            mma16816(acc[2], ahi0, ahi1, ahi2, ahi3, bh23[0], bh23[1]);
            mma16816(acc[3], ahi0, ahi1, ahi2, ahi3, bh23[2], bh23[3]);
            mma16816(acc[0], ahi0, ahi1, ahi2, ahi3, bl01[0], bl01[1]);
            mma16816(acc[1], ahi0, ahi1, ahi2, ahi3, bl01[2], bl01[3]);
            mma16816(acc[2], ahi0, ahi1, ahi2, ahi3, bl23[0], bl23[1]);
            mma16816(acc[3], ahi0, ahi1, ahi2, ahi3, bl23[2], bl23[3]);
            mma16816(acc[0], alo0, alo1, alo2, alo3, bh01[0], bh01[1]);
            mma16816(acc[1], alo0, alo1, alo2, alo3, bh01[2], bh01[3]);
            mma16816(acc[2], alo0, alo1, alo2, alo3, bh23[0], bh23[1]);
            mma16816(acc[3], alo0, alo1, alo2, alo3, bh23[2], bh23[3]);
        }
    }
    float* po = (jh ? part1 : part0) + (size_t)(b * NN + r0) * FF + h * 32;
    #pragma unroll
    for (int nt = 0; nt < 4; ++nt) {
        *(float2*)(po + nt * 8 + 2 * t) = make_float2(acc[nt][0], acc[nt][1]);
        *(float2*)(po + (size_t)8 * FF + nt * 8 + 2 * t) = make_float2(acc[nt][2], acc[nt][3]);
    }
}

// ---------------- BatchNorm over batch (B=4) + ReLU (+residual); sums 2 partials ----------------
template <bool ADDRES>
__global__ __launch_bounds__(256) void bn_k(const float* __restrict__ y0,
                                            const float* __restrict__ y1,
                                            const float* __restrict__ gamma,
                                            const float* __restrict__ beta,
                                            const float* __restrict__ resid,
                                            float* __restrict__ out) {
    const int p = blockIdx.x * 256 + threadIdx.x;
    const float v0 = y0[p]          + y1[p];
    const float v1 = y0[NF + p]     + y1[NF + p];
    const float v2 = y0[2 * NF + p] + y1[2 * NF + p];
    const float v3 = y0[3 * NF + p] + y1[3 * NF + p];
    const float mu = 0.25f * (v0 + v1 + v2 + v3);
    const float d0 = v0 - mu, d1 = v1 - mu, d2 = v2 - mu, d3 = v3 - mu;
    const float var = 0.25f * (d0 * d0 + d1 * d1 + d2 * d2 + d3 * d3);
    const float rs = rsqrtf(var + 1e-5f);
    const float ga = gamma[p] * rs;
    const float be = beta[p];
    float o0 = fmaxf(fmaf(ga, d0, be), 0.f);
    float o1 = fmaxf(fmaf(ga, d1, be), 0.f);
    float o2 = fmaxf(fmaf(ga, d2, be), 0.f);
    float o3 = fmaxf(fmaf(ga, d3, be), 0.f);
    if (ADDRES) {
        o0 += resid[p];
        o1 += resid[NF + p];
        o2 += resid[2 * NF + p];
        o3 += resid[3 * NF + p];
    }
    out[p] = o0;
    out[NF + p] = o1;
    out[2 * NF + p] = o2;
    out[3 * NF + p] = o3;
}

// ---------------- launch (single stream, 9 kernels) ----------------
extern "C" void kernel_launch(void* const* d_in, const int* in_sizes, int n_in,
                              void* d_out, int out_size) {
    const float* x  = (const float*)d_in[0];
    const int*  adj = (const int*)  d_in[1];
    const float* W1 = (const float*)d_in[2];
    const float* a1 = (const float*)d_in[3];
    const float* g1 = (const float*)d_in[4];
    const float* b1 = (const float*)d_in[5];
    const float* W2 = (const float*)d_in[6];
    const float* a2 = (const float*)d_in[7];
    const float* g2 = (const float*)d_in[8];
    const float* b2 = (const float*)d_in[9];
    float* out = (float*)d_out;

    static float *pp0 = nullptr, *pp1, *py, *pex, *pden;
    static unsigned *padjb, *padjbT;
    static __nv_bfloat16 *pgthi, *pgtlo;
    if (!pp0) {
        cudaGetSymbolAddress((void**)&pp0,    p0_buf);
        cudaGetSymbolAddress((void**)&pp1,    p1_buf);
        cudaGetSymbolAddress((void**)&py,     y_buf);
        cudaGetSymbolAddress((void**)&pex,    ex_buf);
        cudaGetSymbolAddress((void**)&pden,   den_buf);
        cudaGetSymbolAddress((void**)&padjb,  adjb_buf);
        cudaGetSymbolAddress((void**)&padjbT, adjbT_buf);
        cudaGetSymbolAddress((void**)&pgthi,  gthi_buf);
        cudaGetSymbolAddress((void**)&pgtlo,  gtlo_buf);
    }
    const int EXN = BB * HH * NN;
    float* pes  = pex;
    float* pes2 = pex + EXN;
    float* ped  = pex + 2 * EXN;
    float* ped2 = pex + 3 * EXN;

    adjprep_k<<<32, dim3(32, 32)>>>(adj, padjb, padjbT);

    // ---- layer 1 ----
    gemm_fused<<<dim3(8, 64), 128>>>(x, W1, a1, pes, pes2, ped, ped2,
                                     pgthi, pgtlo, pden);
    denom_k<<<dim3(16, 8, 4), 512>>>(padjbT, pes, pes2, ped, ped2, pden);
    attn_k<<<dim3(8, 16, 4), 256>>>(padjb, pes, pes2, ped, ped2, pden,
                                    pgthi, pgtlo, pp0, pp1);
    bn_k<false><<<1024, 256>>>(pp0, pp1, g1, b1, nullptr, py);

    // ---- layer 2 ----
    gemm_fused<<<dim3(8, 64), 128>>>(py, W2, a2, pes, pes2, ped, ped2,
                                     pgthi, pgtlo, pden);
    denom_k<<<dim3(16, 8, 4), 512>>>(padjbT, pes, pes2, ped, ped2, pden);
    attn_k<<<dim3(8, 16, 4), 256>>>(padjb, pes, pes2, ped, ped2, pden,
                                    pgthi, pgtlo, pp0, pp1);
    bn_k<true><<<1024, 256>>>(pp0, pp1, g2, b2, x, out);
}

// round 17
// speedup vs baseline: 1.0606x; 1.0606x over previous
#include <cuda_runtime.h>
#include <cuda_bf16.h>
#include <cstdint>

#define BB 4
#define NN 1024
#define FF 256
#define HH 8
#define NF (NN*FF)

// ---------------- scratch (no allocations allowed) ----------------
__device__ float p0_buf [BB*NN*FF];
__device__ float p1_buf [BB*NN*FF];
__device__ float p2_buf [BB*NN*FF];
__device__ float p3_buf [BB*NN*FF];
__device__ float y_buf  [BB*NN*FF];
__device__ float ex_buf [4*BB*HH*NN];   // es, es2, ed, ed2  each [bh][n]
__device__ float den_buf[BB*HH*NN];
__device__ unsigned adjb_buf [NN*32];   // row bits:  adjb[i][jw]
__device__ unsigned adjbT_buf[NN*32];   // col bits:  adjbT[j][iw]
__device__ __nv_bfloat16 gthi_buf[BB*HH*32*NN];   // G^T hi  [bh][d][j]
__device__ __nv_bfloat16 gtlo_buf[BB*HH*32*NN];   // G^T lo

// ---------------- f32x2 helpers ----------------
__device__ __forceinline__ unsigned long long pack2(float a, float b) {
    unsigned long long r;
    asm("mov.b64 %0, {%1, %2};" : "=l"(r) : "f"(a), "f"(b));
    return r;
}
__device__ __forceinline__ void ffma2(unsigned long long& acc,
                                      unsigned long long a, unsigned long long b) {
    asm("fma.rn.f32x2 %0, %1, %2, %0;" : "+l"(acc) : "l"(a), "l"(b));
}
union F4U2 { float4 f; ulonglong2 u; };

// ---------------- mma helpers ----------------
__device__ __forceinline__ uint32_t smem_u32(const void* p) {
    uint32_t a;
    asm("{ .reg .u64 t; cvta.to.shared.u64 t, %1; cvt.u32.u64 %0, t; }" : "=r"(a) : "l"(p));
    return a;
}
__device__ __forceinline__ uint32_t cvt2(float hi, float lo) {
    uint32_t r;
    asm("cvt.rn.bf16x2.f32 %0, %1, %2;" : "=r"(r) : "f"(hi), "f"(lo));
    return r;
}
__device__ __forceinline__ void ldm_x4(uint32_t& r0, uint32_t& r1, uint32_t& r2,
                                       uint32_t& r3, uint32_t addr) {
    asm volatile("ldmatrix.sync.aligned.m8n8.x4.shared.b16 {%0,%1,%2,%3}, [%4];"
                 : "=r"(r0), "=r"(r1), "=r"(r2), "=r"(r3) : "r"(addr));
}
__device__ __forceinline__ void mma16816(float* c, uint32_t a0, uint32_t a1,
                                         uint32_t a2, uint32_t a3,
                                         uint32_t b0, uint32_t b1) {
    asm volatile(
        "mma.sync.aligned.m16n8k16.row.col.f32.bf16.bf16.f32 "
        "{%0,%1,%2,%3}, {%4,%5,%6,%7}, {%8,%9}, {%0,%1,%2,%3};"
        : "+f"(c[0]), "+f"(c[1]), "+f"(c[2]), "+f"(c[3])
        : "r"(a0), "r"(a1), "r"(a2), "r"(a3), "r"(b0), "r"(b1));
}

// ---------------- fused GEMM (64x64) + gt-transpose + src/dst exp tables + den zero ----------------
__global__ __launch_bounds__(256) void gemm_fused(const float* __restrict__ A,
                                                  const float* __restrict__ W,
                                                  const float* __restrict__ av,
                                                  float* __restrict__ es,
                                                  float* __restrict__ es2,
                                                  float* __restrict__ ed,
                                                  float* __restrict__ ed2,
                                                  __nv_bfloat16* __restrict__ gthi,
                                                  __nv_bfloat16* __restrict__ gtlo,
                                                  float* __restrict__ den) {
    __shared__ float As[16][68];
    __shared__ float Bs[16][68];
    __shared__ uint32_t T[64][65];
    const int m0 = blockIdx.y * 64;
    const int o0 = blockIdx.x * 64;
    const int tid = threadIdx.x;
    const int tx = tid & 15;
    const int ty = tid >> 4;

    const int gtid = (blockIdx.y * 4 + blockIdx.x) * 256 + tid;
    if (gtid < BB * HH * NN) den[gtid] = 0.f;

    unsigned long long acc2[4][2];
    #pragma unroll
    for (int a = 0; a < 4; a++) { acc2[a][0] = 0ull; acc2[a][1] = 0ull; }
    for (int k0 = 0; k0 < 256; k0 += 16) {
        const int c = tid & 15;
        const int r = tid >> 4;
        #pragma unroll
        for (int rr = 0; rr < 64; rr += 16) {
            As[c][r + rr] = A[(m0 + r + rr) * 256 + k0 + c];
            Bs[c][r + rr] = W[(o0 + r + rr) * 256 + k0 + c];
        }
        __syncthreads();
        #pragma unroll
        for (int kk = 0; kk < 16; kk++) {
            F4U2 a4, b4;
            a4.f = *(const float4*)&As[kk][ty * 4];
            b4.f = *(const float4*)&Bs[kk][tx * 4];
            const unsigned long long ap0 = pack2(a4.f.x, a4.f.x);
            const unsigned long long ap1 = pack2(a4.f.y, a4.f.y);
            const unsigned long long ap2 = pack2(a4.f.z, a4.f.z);
            const unsigned long long ap3 = pack2(a4.f.w, a4.f.w);
            ffma2(acc2[0][0], ap0, b4.u.x); ffma2(acc2[0][1], ap0, b4.u.y);
            ffma2(acc2[1][0], ap1, b4.u.x); ffma2(acc2[1][1], ap1, b4.u.y);
            ffma2(acc2[2][0], ap2, b4.u.x); ffma2(acc2[2][1], ap2, b4.u.y);
            ffma2(acc2[3][0], ap3, b4.u.x); ffma2(acc2[3][1], ap3, b4.u.y);
        }
        __syncthreads();
    }

    const int b  = m0 >> 10;
    const int j0 = m0 & 1023;
    const int h0 = o0 >> 5;

    float aws[4], awd[4];
    #pragma unroll
    for (int c = 0; c < 4; ++c) {
        const int d = (tx * 4 + c) & 31;
        aws[c] = av[d];
        awd[c] = av[32 + d];
    }

    float vv[4][4];
    #pragma unroll
    for (int a = 0; a < 4; a++) {
        F4U2 o;
        o.u.x = acc2[a][0];
        o.u.y = acc2[a][1];
        vv[a][0] = o.f.x; vv[a][1] = o.f.y; vv[a][2] = o.f.z; vv[a][3] = o.f.w;
        #pragma unroll
        for (int c = 0; c < 4; ++c) {
            const __nv_bfloat16 hi = __float2bfloat16(vv[a][c]);
            const __nv_bfloat16 lo = __float2bfloat16(vv[a][c] - __bfloat162float(hi));
            T[tx * 4 + c][ty * 4 + a] = (uint32_t)__bfloat16_as_ushort(hi)
                                      | ((uint32_t)__bfloat16_as_ushort(lo) << 16);
        }
    }

    #pragma unroll
    for (int a = 0; a < 4; a++) {
        float s = vv[a][0] * aws[0] + vv[a][1] * aws[1]
                + vv[a][2] * aws[2] + vv[a][3] * aws[3];
        float d = vv[a][0] * awd[0] + vv[a][1] * awd[1]
                + vv[a][2] * awd[2] + vv[a][3] * awd[3];
        #pragma unroll
        for (int off = 4; off; off >>= 1) {
            s += __shfl_down_sync(0xFFFFFFFFu, s, off, 8);
            d += __shfl_down_sync(0xFFFFFFFFu, d, off, 8);
        }
        if ((tx & 7) == 0) {
            const int h = h0 + (tx >> 3);
            const int n = j0 + ty * 4 + a;
            const int idx = (b * HH + h) * NN + n;
            es [idx] = __expf(s);
            es2[idx] = __expf(0.2f * s);
            ed [idx] = __expf(d);
            ed2[idx] = __expf(0.2f * d);
        }
    }

    __syncthreads();
    {
        const int dl = tid >> 2;
        const int mq = (tid & 3) * 16;
        __align__(16) unsigned short his[16];
        __align__(16) unsigned short los[16];
        #pragma unroll
        for (int k = 0; k < 16; ++k) {
            const uint32_t v = T[dl][mq + k];
            his[k] = (unsigned short)(v & 0xFFFF);
            los[k] = (unsigned short)(v >> 16);
        }
        const int h = h0 + (dl >> 5);
        const int d = dl & 31;
        const size_t base = (size_t)((b * HH + h) * 32 + d) * NN + j0 + mq;
        *(uint4*)&gthi[base]     = ((uint4*)his)[0];
        *(uint4*)&gthi[base + 8] = ((uint4*)his)[1];
        *(uint4*)&gtlo[base]     = ((uint4*)los)[0];
        *(uint4*)&gtlo[base + 8] = ((uint4*)los)[1];
    }
}

// ---------------- adj -> row + column bitmasks (one kernel) ----------------
__global__ __launch_bounds__(1024) void adjprep_k(const int* __restrict__ adj,
                                                  unsigned* __restrict__ adjb,
                                                  unsigned* __restrict__ adjbT) {
    __shared__ unsigned tileW[32][33];
    const int lane = threadIdx.x;
    const int wy   = threadIdx.y;
    const int i    = blockIdx.x * 32 + wy;
    #pragma unroll 4
    for (int w = 0; w < 32; ++w) {
        const int v = adj[i * 1024 + w * 32 + lane];
        const unsigned m = __ballot_sync(0xFFFFFFFFu, v != 0);
        if (lane == 0) {
            adjb[i * 32 + w] = m;
            tileW[wy][w] = m;
        }
    }
    __syncthreads();
    const unsigned wrd = tileW[lane][wy];
    #pragma unroll 4
    for (int c = 0; c < 32; ++c) {
        const unsigned m2 = __ballot_sync(0xFFFFFFFFu, (wrd >> c) & 1u);
        if (lane == c) adjbT[(wy * 32 + c) * 32 + blockIdx.x] = m2;
    }
}

// ---------------- den[bh][j] += sum_{i chunk} adj * max(es*ed, es2*ed2) ----------------
__global__ __launch_bounds__(512) void denom_k(const unsigned* __restrict__ adjbT,
                                               const float* __restrict__ es,
                                               const float* __restrict__ es2,
                                               const float* __restrict__ ed,
                                               const float* __restrict__ ed2,
                                               float* __restrict__ den) {
    __shared__ float2 essv[64];
    const int b = blockIdx.z, h = blockIdx.y, bh = b * HH + h;
    const int ic = blockIdx.x * 64;
    const int tid = threadIdx.x;
    if (tid < 64) essv[tid] = make_float2(es[bh * NN + ic + tid],
                                          es2[bh * NN + ic + tid]);
    __syncthreads();
    const int j0 = tid, j1 = tid + 512;
    const float edj0 = ed[bh * NN + j0], ed2j0 = ed2[bh * NN + j0];
    const float edj1 = ed[bh * NN + j1], ed2j1 = ed2[bh * NN + j1];
    const int wbase = ic >> 5;
    float a0 = 0.f, a1 = 0.f;
    #pragma unroll
    for (int w = 0; w < 2; ++w) {
        const unsigned word0 = adjbT[(size_t)j0 * 32 + wbase + w];
        const unsigned word1 = adjbT[(size_t)j1 * 32 + wbase + w];
        #pragma unroll
        for (int k = 0; k < 32; ++k) {
            const float2 e = essv[w * 32 + k];
            const float v0 = fmaxf(e.x * edj0, e.y * ed2j0);
            const float v1 = fmaxf(e.x * edj1, e.y * ed2j1);
            if ((word0 >> k) & 1u) a0 += v0;
            if ((word1 >> k) & 1u) a1 += v1;
        }
    }
    atomicAdd(&den[bh * NN + j0], a0);
    atomicAdd(&den[bh * NN + j1], a1);
}

// ---------------- attention via mma.sync bf16 (hi/lo 3-term), j-split x4 ----------------
// block = 8 warps x 16 i = 128 i rows, one (b, h, j-quarter). grid (8, 32, 4).
#define GROW 272

__device__ __forceinline__ float wv(float esr, float es2r, float2 e,
                                    unsigned bits, int c) {
    const float v = fmaxf(esr * e.x, es2r * e.y);
    return ((bits >> c) & 1u) ? v : 0.0f;
}

__global__ __launch_bounds__(256) void attn_k(const unsigned* __restrict__ adjb,
                                              const float* __restrict__ es,
                                              const float* __restrict__ es2,
                                              const float* __restrict__ ed,
                                              const float* __restrict__ ed2,
                                              const float* __restrict__ den,
                                              const __nv_bfloat16* __restrict__ gthi,
                                              const __nv_bfloat16* __restrict__ gtlo,
                                              float* __restrict__ part0,
                                              float* __restrict__ part1,
                                              float* __restrict__ part2,
                                              float* __restrict__ part3) {
    __shared__ __align__(16) char GsHi[32 * GROW];
    __shared__ __align__(16) char GsLo[32 * GROW];
    __shared__ float2 eds[NN / 4];
    __shared__ unsigned adjw[128][9];
    const int b = blockIdx.z;
    const int h = blockIdx.y & 7, jh = blockIdx.y >> 3;   // jh 0..3
    const int bh = b * HH + h;
    const int jbase = jh * (NN / 4);
    const int i0 = blockIdx.x * 128;
    const int tid = threadIdx.x, wid = tid >> 5, lane = tid & 31;
    const int g = lane >> 2, t = lane & 3;

    for (int j = tid; j < NN / 4; j += 256) {
        const float r = 1.0f / den[bh * NN + jbase + j];
        eds[j] = make_float2(ed[bh * NN + jbase + j] * r,
                             ed2[bh * NN + jbase + j] * r);
    }
    for (int k = tid; k < 128 * 8; k += 256)
        adjw[k >> 3][k & 7] = adjb[(size_t)(i0 + (k >> 3)) * 32 + jh * 8 + (k & 7)];

    const int r0 = i0 + wid * 16 + g;
    const float es_0  = es [bh * NN + r0];
    const float es_1  = es [bh * NN + r0 + 8];
    const float es2_0 = es2[bh * NN + r0];
    const float es2_1 = es2[bh * NN + r0 + 8];

    float acc[4][4] = {};
    const uint32_t gsHiA = smem_u32(GsHi), gsLoA = smem_u32(GsLo);
    const int d_l  = ((lane >> 4) & 1) * 8 + (lane & 7);
    const int jo_l = ((lane >> 3) & 1) * 8;
    const uint32_t lmoff = (uint32_t)(d_l * GROW + jo_l * 2);

    const __nv_bfloat16* ghb = gthi + (size_t)bh * 32 * NN + jbase;
    const __nv_bfloat16* glb = gtlo + (size_t)bh * 32 * NN + jbase;

    for (int ck = 0; ck < NN / 4; ck += 128) {
        __syncthreads();
        #pragma unroll
        for (int q = 0; q < 2; ++q) {
            const int idx = tid + q * 256;
            const int d = idx >> 4, c16 = idx & 15;
            const uint4 vh = *(const uint4*)(ghb + (size_t)d * NN + ck + c16 * 8);
            const uint4 vl = *(const uint4*)(glb + (size_t)d * NN + ck + c16 * 8);
            *(uint4*)(GsHi + d * GROW + c16 * 16) = vh;
            *(uint4*)(GsLo + d * GROW + c16 * 16) = vl;
        }
        __syncthreads();
        unsigned cw0[4], cw1[4];
        #pragma unroll
        for (int w = 0; w < 4; ++w) {
            cw0[w] = adjw[wid * 16 + g][(ck >> 5) + w];
            cw1[w] = adjw[wid * 16 + g + 8][(ck >> 5) + w];
        }
        #pragma unroll
        for (int kk = 0; kk < 128; kk += 16) {
            uint32_t bh01[4], bh23[4], bl01[4], bl23[4];
            ldm_x4(bh01[0], bh01[1], bh01[2], bh01[3], gsHiA + lmoff + kk * 2);
            ldm_x4(bh23[0], bh23[1], bh23[2], bh23[3], gsHiA + lmoff + kk * 2 + 16 * GROW);
            ldm_x4(bl01[0], bl01[1], bl01[2], bl01[3], gsLoA + lmoff + kk * 2);
            ldm_x4(bl23[0], bl23[1], bl23[2], bl23[3], gsLoA + lmoff + kk * 2 + 16 * GROW);
            const unsigned bits0 = cw0[kk >> 5] >> (kk & 31);
            const unsigned bits1 = cw1[kk >> 5] >> (kk & 31);
            const int jc = ck + kk;
            const float2 e0 = eds[jc + 2 * t];
            const float2 e1 = eds[jc + 2 * t + 1];
            const float2 e2 = eds[jc + 2 * t + 8];
            const float2 e3 = eds[jc + 2 * t + 9];
            const float w00 = wv(es_0, es2_0, e0, bits0, 2 * t);
            const float w01 = wv(es_0, es2_0, e1, bits0, 2 * t + 1);
            const float w02 = wv(es_0, es2_0, e2, bits0, 2 * t + 8);
            const float w03 = wv(es_0, es2_0, e3, bits0, 2 * t + 9);
            const float w10 = wv(es_1, es2_1, e0, bits1, 2 * t);
            const float w11 = wv(es_1, es2_1, e1, bits1, 2 * t + 1);
            const float w12 = wv(es_1, es2_1, e2, bits1, 2 * t + 8);
            const float w13 = wv(es_1, es2_1, e3, bits1, 2 * t + 9);
            const uint32_t ahi0 = cvt2(w01, w00);
            const uint32_t ahi1 = cvt2(w11, w10);
            const uint32_t ahi2 = cvt2(w03, w02);
            const uint32_t ahi3 = cvt2(w13, w12);
            const uint32_t alo0 = cvt2(w01 - __uint_as_float(ahi0 & 0xFFFF0000u),
                                       w00 - __uint_as_float(ahi0 << 16));
            const uint32_t alo1 = cvt2(w11 - __uint_as_float(ahi1 & 0xFFFF0000u),
                                       w10 - __uint_as_float(ahi1 << 16));
            const uint32_t alo2 = cvt2(w03 - __uint_as_float(ahi2 & 0xFFFF0000u),
                                       w02 - __uint_as_float(ahi2 << 16));
            const uint32_t alo3 = cvt2(w13 - __uint_as_float(ahi3 & 0xFFFF0000u),
                                       w12 - __uint_as_float(ahi3 << 16));
            mma16816(acc[0], ahi0, ahi1, ahi2, ahi3, bh01[0], bh01[1]);
            mma16816(acc[1], ahi0, ahi1, ahi2, ahi3, bh01[2], bh01[3]);
            mma16816(acc[2], ahi0, ahi1, ahi2, ahi3, bh23[0], bh23[1]);
            mma16816(acc[3], ahi0, ahi1, ahi2, ahi3, bh23[2], bh23[3]);
            mma16816(acc[0], ahi0, ahi1, ahi2, ahi3, bl01[0], bl01[1]);
            mma16816(acc[1], ahi0, ahi1, ahi2, ahi3, bl01[2], bl01[3]);
            mma16816(acc[2], ahi0, ahi1, ahi2, ahi3, bl23[0], bl23[1]);
            mma16816(acc[3], ahi0, ahi1, ahi2, ahi3, bl23[2], bl23[3]);
            mma16816(acc[0], alo0, alo1, alo2, alo3, bh01[0], bh01[1]);
            mma16816(acc[1], alo0, alo1, alo2, alo3, bh01[2], bh01[3]);
            mma16816(acc[2], alo0, alo1, alo2, alo3, bh23[0], bh23[1]);
            mma16816(acc[3], alo0, alo1, alo2, alo3, bh23[2], bh23[3]);
        }
    }
    float* pp = (jh == 0) ? part0 : (jh == 1) ? part1 : (jh == 2) ? part2 : part3;
    float* po = pp + (size_t)(b * NN + r0) * FF + h * 32;
    #pragma unroll
    for (int nt = 0; nt < 4; ++nt) {
        *(float2*)(po + nt * 8 + 2 * t) = make_float2(acc[nt][0], acc[nt][1]);
        *(float2*)(po + (size_t)8 * FF + nt * 8 + 2 * t) = make_float2(acc[nt][2], acc[nt][3]);
    }
}

// ---------------- BatchNorm over batch (B=4) + ReLU (+residual); sums 4 partials ----------------
template <bool ADDRES>
__global__ __launch_bounds__(256) void bn_k(const float* __restrict__ y0,
                                            const float* __restrict__ y1,
                                            const float* __restrict__ y2,
                                            const float* __restrict__ y3,
                                            const float* __restrict__ gamma,
                                            const float* __restrict__ beta,
                                            const float* __restrict__ resid,
                                            float* __restrict__ out) {
    const int p = blockIdx.x * 256 + threadIdx.x;
    const float v0 = (y0[p]          + y1[p])          + (y2[p]          + y3[p]);
    const float v1 = (y0[NF + p]     + y1[NF + p])     + (y2[NF + p]     + y3[NF + p]);
    const float v2 = (y0[2 * NF + p] + y1[2 * NF + p]) + (y2[2 * NF + p] + y3[2 * NF + p]);
    const float v3 = (y0[3 * NF + p] + y1[3 * NF + p]) + (y2[3 * NF + p] + y3[3 * NF + p]);
    const float mu = 0.25f * (v0 + v1 + v2 + v3);
    const float d0 = v0 - mu, d1 = v1 - mu, d2 = v2 - mu, d3 = v3 - mu;
    const float var = 0.25f * (d0 * d0 + d1 * d1 + d2 * d2 + d3 * d3);
    const float rs = rsqrtf(var + 1e-5f);
    const float ga = gamma[p] * rs;
    const float be = beta[p];
    float o0 = fmaxf(fmaf(ga, d0, be), 0.f);
    float o1 = fmaxf(fmaf(ga, d1, be), 0.f);
    float o2 = fmaxf(fmaf(ga, d2, be), 0.f);
    float o3 = fmaxf(fmaf(ga, d3, be), 0.f);
    if (ADDRES) {
        o0 += resid[p];
        o1 += resid[NF + p];
        o2 += resid[2 * NF + p];
        o3 += resid[3 * NF + p];
    }
    out[p] = o0;
    out[NF + p] = o1;
    out[2 * NF + p] = o2;
    out[3 * NF + p] = o3;
}

// ---------------- launch (single stream, 9 kernels) ----------------
extern "C" void kernel_launch(void* const* d_in, const int* in_sizes, int n_in,
                              void* d_out, int out_size) {
    const float* x  = (const float*)d_in[0];
    const int*  adj = (const int*)  d_in[1];
    const float* W1 = (const float*)d_in[2];
    const float* a1 = (const float*)d_in[3];
    const float* g1 = (const float*)d_in[4];
    const float* b1 = (const float*)d_in[5];
    const float* W2 = (const float*)d_in[6];
    const float* a2 = (const float*)d_in[7];
    const float* g2 = (const float*)d_in[8];
    const float* b2 = (const float*)d_in[9];
    float* out = (float*)d_out;

    static float *pp0 = nullptr, *pp1, *pp2, *pp3, *py, *pex, *pden;
    static unsigned *padjb, *padjbT;
    static __nv_bfloat16 *pgthi, *pgtlo;
    if (!pp0) {
        cudaGetSymbolAddress((void**)&pp0,    p0_buf);
        cudaGetSymbolAddress((void**)&pp1,    p1_buf);
        cudaGetSymbolAddress((void**)&pp2,    p2_buf);
        cudaGetSymbolAddress((void**)&pp3,    p3_buf);
        cudaGetSymbolAddress((void**)&py,     y_buf);
        cudaGetSymbolAddress((void**)&pex,    ex_buf);
        cudaGetSymbolAddress((void**)&pden,   den_buf);
        cudaGetSymbolAddress((void**)&padjb,  adjb_buf);
        cudaGetSymbolAddress((void**)&padjbT, adjbT_buf);
        cudaGetSymbolAddress((void**)&pgthi,  gthi_buf);
        cudaGetSymbolAddress((void**)&pgtlo,  gtlo_buf);
    }
    const int EXN = BB * HH * NN;
    float* pes  = pex;
    float* pes2 = pex + EXN;
    float* ped  = pex + 2 * EXN;
    float* ped2 = pex + 3 * EXN;

    adjprep_k<<<32, dim3(32, 32)>>>(adj, padjb, padjbT);

    // ---- layer 1 ----
    gemm_fused<<<dim3(4, 64), 256>>>(x, W1, a1, pes, pes2, ped, ped2,
                                     pgthi, pgtlo, pden);
    denom_k<<<dim3(16, 8, 4), 512>>>(padjbT, pes, pes2, ped, ped2, pden);
    attn_k<<<dim3(8, 32, 4), 256>>>(padjb, pes, pes2, ped, ped2, pden,
                                    pgthi, pgtlo, pp0, pp1, pp2, pp3);
    bn_k<false><<<1024, 256>>>(pp0, pp1, pp2, pp3, g1, b1, nullptr, py);

    // ---- layer 2 ----
    gemm_fused<<<dim3(4, 64), 256>>>(py, W2, a2, pes, pes2, ped, ped2,
                                     pgthi, pgtlo, pden);
    denom_k<<<dim3(16, 8, 4), 512>>>(padjbT, pes, pes2, ped, ped2, pden);
    attn_k<<<dim3(8, 32, 4), 256>>>(padjb, pes, pes2, ped, ped2, pden,
                                    pgthi, pgtlo, pp0, pp1, pp2, pp3);
    bn_k<true><<<1024, 256>>>(pp0, pp1, pp2, pp3, g2, b2, x, out);
}